// round 15
// baseline (speedup 1.0000x reference)
#include <cuda_runtime.h>
#include <cuda_fp16.h>
#include <math.h>
#include <cstdint>

// Problem constants
#define BB 2
#define SS 2048
#define EE 2048
#define HH_ 16
#define DD 128
#define E3 (3*EE)

// Scratch (allocation-free rule: __device__ globals)
__device__ __half g_qkvh[(long)BB*SS*E3];   // half qkv (gemm out, rope in-place, FA in)
__device__ __half g_ctxh[(long)BB*SS*EE];   // half ctx (FA out, out-proj in)
__device__ __half g_xh [(long)BB*SS*EE];
__device__ __half g_w1h[(long)E3*EE];
__device__ __half g_w2h[(long)EE*EE];

__device__ __forceinline__ void mma16(float* d, const uint32_t* a, const uint32_t* b) {
    asm volatile("mma.sync.aligned.m16n8k16.row.col.f32.f16.f16.f32 "
        "{%0,%1,%2,%3}, {%4,%5,%6,%7}, {%8,%9}, {%0,%1,%2,%3};"
        : "+f"(d[0]), "+f"(d[1]), "+f"(d[2]), "+f"(d[3])
        : "r"(a[0]), "r"(a[1]), "r"(a[2]), "r"(a[3]), "r"(b[0]), "r"(b[1]));
}
__device__ __forceinline__ void ldsm4(uint32_t* r, uint32_t addr) {
    asm volatile("ldmatrix.sync.aligned.m8n8.x4.shared.b16 {%0,%1,%2,%3}, [%4];"
        : "=r"(r[0]), "=r"(r[1]), "=r"(r[2]), "=r"(r[3]) : "r"(addr));
}
__device__ __forceinline__ void ldsm4t(uint32_t* r, uint32_t addr) {
    asm volatile("ldmatrix.sync.aligned.m8n8.x4.trans.shared.b16 {%0,%1,%2,%3}, [%4];"
        : "=r"(r[0]), "=r"(r[1]), "=r"(r[2]), "=r"(r[3]) : "r"(addr));
}
__device__ __forceinline__ uint32_t smem_u32(const void* p) {
    uint32_t a;
    asm("{ .reg .u64 t; cvta.to.shared.u64 t, %1; cvt.u32.u64 %0, t; }"
        : "=r"(a) : "l"(p));
    return a;
}
__device__ __forceinline__ uint32_t h2pack(float lo, float hi) {
    __half2 h = __floats2half2_rn(lo, hi);
    return *(uint32_t*)&h;
}
#define CP_ASYNC16(dst, src) \
    asm volatile("cp.async.ca.shared.global [%0], [%1], 16;" :: "r"(dst), "l"(src))
#define CP_COMMIT() asm volatile("cp.async.commit_group;" ::: "memory")
#define CP_WAIT(n)  asm volatile("cp.async.wait_group %0;" :: "n"(n) : "memory")

// ---------------------------------------------------------------------------
// fp32 -> fp16 round-copy (8 floats / thread)
// ---------------------------------------------------------------------------
__global__ __launch_bounds__(256)
void h16copy_k(const float* __restrict__ in, __half* __restrict__ out)
{
    long i = ((long)blockIdx.x*256 + threadIdx.x) * 8;
    float4 v0 = *(const float4*)(in + i);
    float4 v1 = *(const float4*)(in + i + 4);
    __half2 h0 = __floats2half2_rn(v0.x, v0.y);
    __half2 h1 = __floats2half2_rn(v0.z, v0.w);
    __half2 h2 = __floats2half2_rn(v1.x, v1.y);
    __half2 h3 = __floats2half2_rn(v1.z, v1.w);
    uint4 o;
    o.x = *(uint32_t*)&h0; o.y = *(uint32_t*)&h1;
    o.z = *(uint32_t*)&h2; o.w = *(uint32_t*)&h3;
    *(uint4*)(out + i) = o;
}

#define LDH 72                      // halves; 36 words -> 4-bank shift/row

// ===========================================================================
// QKV GEMM: 128x96 tile, 8 warps (4x2), warp 32x48, BK=64, 3-stage cp.async,
// 2 CTAs/SM (96.8 KB smem, <=128 regs). Grid 64x32 = 2048 CTAs = 6.92 waves
// at 296 concurrent. Output written as half directly (rope rotates in place).
// ===========================================================================
#define Q_BN 96
#define Q_A_ST (128*LDH)            // 9216 halves
#define Q_B_ST (Q_BN*LDH)           // 6912 halves
#define Q_STH  (Q_A_ST + Q_B_ST)    // 16128 halves / stage
#define SMEM_QKV (3*Q_STH*2)        // 96768 bytes

__global__ __launch_bounds__(256, 2)
void tqkv96(const __half* __restrict__ gA, const __half* __restrict__ gB,
            __half* __restrict__ gCh, const float* __restrict__ bias,
            int K, int lda, int ldb, int ldc)
{
    extern __shared__ __half smh[];
    int m0 = blockIdx.y * 128;
    int n0 = blockIdx.x * Q_BN;
    int niter = K / 64;

    int tid  = threadIdx.x;
    int wid  = tid >> 5;
    int lane = tid & 31;
    int wm = wid & 3;               // 4 slabs of 32 rows
    int wn = wid >> 2;              // 2 slabs of 48 cols
    int gq = lane >> 2;
    int tg = lane & 3;

    int a_row = (lane & 7) + ((lane >> 3) & 1) * 8;
    int a_col = (lane >> 4) * 8;
    int b_row = (lane & 7) + (lane >> 4) * 8;
    int b_col = ((lane >> 3) & 1) * 8;
    uint32_t smbase = smem_u32(smh);
    uint32_t aoff = ((wm*32 + a_row) * LDH + a_col) * 2;
    uint32_t boff = (uint32_t)(Q_A_ST*2) + ((wn*48 + b_row) * LDH + b_col) * 2;

    float acc[2][6][4];
    #pragma unroll
    for (int mt = 0; mt < 2; mt++)
        #pragma unroll
        for (int nt = 0; nt < 6; nt++)
            #pragma unroll
            for (int r = 0; r < 4; r++) acc[mt][nt][r] = 0.f;

    auto issue = [&](int it) {
        int k0 = it * 64;
        __half* As = smh + (it % 3) * Q_STH;
        __half* Bs = As + Q_A_ST;
        const __half* Ab = gA + (long)m0 * lda + k0;
        #pragma unroll
        for (int p = 0; p < 4; p++) {        // 128 rows x 8 chunks
            int idx = p * 256 + tid;
            int r = idx >> 3, c8 = (idx & 7) << 3;
            CP_ASYNC16(smem_u32(As + r * LDH + c8), Ab + (long)r * lda + c8);
        }
        const __half* Bb = gB + (long)n0 * ldb + k0;
        #pragma unroll
        for (int p = 0; p < 3; p++) {        // 96 rows x 8 chunks
            int idx = p * 256 + tid;
            int r = idx >> 3, c8 = (idx & 7) << 3;
            CP_ASYNC16(smem_u32(Bs + r * LDH + c8), Bb + (long)r * ldb + c8);
        }
        CP_COMMIT();
    };

    auto compute = [&](int s) {
        uint32_t a_base = smbase + s*(Q_STH*2) + aoff;
        uint32_t b_base = smbase + s*(Q_STH*2) + boff;
        #pragma unroll
        for (int ks = 0; ks < 4; ks++) {
            uint32_t kcb = ks * 32;
            uint32_t a[2][4], b[3][4];
            #pragma unroll
            for (int mt = 0; mt < 2; mt++)
                ldsm4(a[mt], a_base + mt*(16*LDH*2) + kcb);
            #pragma unroll
            for (int np = 0; np < 3; np++)
                ldsm4(b[np], b_base + np*(16*LDH*2) + kcb);
            #pragma unroll
            for (int mt = 0; mt < 2; mt++)
                #pragma unroll
                for (int np = 0; np < 3; np++) {
                    mma16(acc[mt][2*np],   a[mt], &b[np][0]);
                    mma16(acc[mt][2*np+1], a[mt], &b[np][2]);
                }
        }
    };

    issue(0);
    if (niter > 1) issue(1);
    for (int it = 0; it < niter; ++it) {
        if (it + 1 < niter) CP_WAIT(1); else CP_WAIT(0);
        __syncthreads();
        if (it + 2 < niter) issue(it + 2);
        compute(it % 3);
    }

    #pragma unroll
    for (int mt = 0; mt < 2; mt++) {
        int row = m0 + wm*32 + mt*16 + gq;
        #pragma unroll
        for (int nt = 0; nt < 6; nt++) {
            int col = n0 + wn*48 + nt*8 + 2*tg;
            float b0 = bias[col], b1 = bias[col + 1];
            *(__half2*)(gCh + (long)row * ldc + col)
                = __floats2half2_rn(acc[mt][nt][0] + b0, acc[mt][nt][1] + b1);
            *(__half2*)(gCh + (long)(row + 8) * ldc + col)
                = __floats2half2_rn(acc[mt][nt][2] + b0, acc[mt][nt][3] + b1);
        }
    }
}

// ===========================================================================
// Out-proj GEMM: 128x256, 8 warps (2x4), warp 64x64, BK=64, 3-stage, fp32 out.
// ===========================================================================
#define O_BN 256
#define O_A_ST (128*LDH)
#define O_B_ST (O_BN*LDH)
#define O_STH  (O_A_ST + O_B_ST)
#define SMEM_OUT (3*O_STH*2)        // 165888 bytes

__global__ __launch_bounds__(256)
void tout256(const __half* __restrict__ gA, const __half* __restrict__ gB,
             float* __restrict__ gC, const float* __restrict__ bias,
             int K, int lda, int ldb, int ldc)
{
    extern __shared__ __half smh[];
    int m0 = blockIdx.y * 128;
    int n0 = blockIdx.x * O_BN;
    int niter = K / 64;

    int tid  = threadIdx.x;
    int wid  = tid >> 5;
    int lane = tid & 31;
    int wm = wid & 1;
    int wn = wid >> 1;
    int gq = lane >> 2;
    int tg = lane & 3;

    int a_row = (lane & 7) + ((lane >> 3) & 1) * 8;
    int a_col = (lane >> 4) * 8;
    int b_row = (lane & 7) + (lane >> 4) * 8;
    int b_col = ((lane >> 3) & 1) * 8;
    uint32_t smbase = smem_u32(smh);
    uint32_t aoff = ((wm*64 + a_row) * LDH + a_col) * 2;
    uint32_t boff = (uint32_t)(O_A_ST*2) + ((wn*64 + b_row) * LDH + b_col) * 2;

    float acc[4][8][4];
    #pragma unroll
    for (int mt = 0; mt < 4; mt++)
        #pragma unroll
        for (int nt = 0; nt < 8; nt++)
            #pragma unroll
            for (int r = 0; r < 4; r++) acc[mt][nt][r] = 0.f;

    auto issue = [&](int it) {
        int k0 = it * 64;
        __half* As = smh + (it % 3) * O_STH;
        __half* Bs = As + O_A_ST;
        const __half* Ab = gA + (long)m0 * lda + k0;
        #pragma unroll
        for (int p = 0; p < 4; p++) {
            int idx = p * 256 + tid;
            int r = idx >> 3, c8 = (idx & 7) << 3;
            CP_ASYNC16(smem_u32(As + r * LDH + c8), Ab + (long)r * lda + c8);
        }
        const __half* Bb = gB + (long)n0 * ldb + k0;
        #pragma unroll
        for (int p = 0; p < 8; p++) {
            int idx = p * 256 + tid;
            int r = idx >> 3, c8 = (idx & 7) << 3;
            CP_ASYNC16(smem_u32(Bs + r * LDH + c8), Bb + (long)r * ldb + c8);
        }
        CP_COMMIT();
    };

    auto compute = [&](int s) {
        uint32_t a_base = smbase + s*(O_STH*2) + aoff;
        uint32_t b_base = smbase + s*(O_STH*2) + boff;
        #pragma unroll
        for (int ks = 0; ks < 4; ks++) {
            uint32_t kcb = ks * 32;
            uint32_t a[4][4], b[4][4];
            #pragma unroll
            for (int mt = 0; mt < 4; mt++)
                ldsm4(a[mt], a_base + mt*(16*LDH*2) + kcb);
            #pragma unroll
            for (int np = 0; np < 4; np++)
                ldsm4(b[np], b_base + np*(16*LDH*2) + kcb);
            #pragma unroll
            for (int mt = 0; mt < 4; mt++)
                #pragma unroll
                for (int np = 0; np < 4; np++) {
                    mma16(acc[mt][2*np],   a[mt], &b[np][0]);
                    mma16(acc[mt][2*np+1], a[mt], &b[np][2]);
                }
        }
    };

    issue(0);
    if (niter > 1) issue(1);
    for (int it = 0; it < niter; ++it) {
        if (it + 1 < niter) CP_WAIT(1); else CP_WAIT(0);
        __syncthreads();
        if (it + 2 < niter) issue(it + 2);
        compute(it % 3);
    }

    #pragma unroll
    for (int mt = 0; mt < 4; mt++) {
        int row = m0 + wm*64 + mt*16 + gq;
        #pragma unroll
        for (int nt = 0; nt < 8; nt++) {
            int col = n0 + wn*64 + nt*8 + 2*tg;
            float b0 = bias[col], b1 = bias[col + 1];
            float2 v0, v1;
            v0.x = acc[mt][nt][0] + b0; v0.y = acc[mt][nt][1] + b1;
            v1.x = acc[mt][nt][2] + b0; v1.y = acc[mt][nt][3] + b1;
            *(float2*)(gC + (long)row * ldc + col)       = v0;
            *(float2*)(gC + (long)(row + 8) * ldc + col) = v1;
        }
    }
}

// ===========================================================================
// fp16 flash attention, 128-col K-tiles; P in registers; K AND V double-
// buffered -> single barrier + single commit group per iteration.
// Smem halves: Q | K0 | K1 | V0 | V1, each 128x136 = 87040 halves = 174080 B
// ===========================================================================
#define FQ_LDH 136
#define FA_K0_H (128*FQ_LDH)
#define FA_K1_H (FA_K0_H + 128*FQ_LDH)
#define FA_V0_H (FA_K1_H + 128*FQ_LDH)
#define FA_V1_H (FA_V0_H + 128*FQ_LDH)
#define FA_SMEM ((FA_V1_H + 128*FQ_LDH)*2)

__global__ __launch_bounds__(256)
void fa_k(const __half* __restrict__ qkv, __half* __restrict__ ctx)
{
    extern __shared__ __half smh[];
    __half* Qs = smh;

    int qt = gridDim.x - 1 - blockIdx.x;       // heavy tiles first
    int bh = blockIdx.y;
    int b = bh >> 4, h = bh & 15;
    const __half* qb = qkv + (long)b*SS*E3 + (long)h*DD;

    int tid = threadIdx.x, wid = tid >> 5, lane = tid & 31;
    int gq = lane >> 2, tg = lane & 3;

    int a_row = (lane & 7) + ((lane >> 3) & 1) * 8;
    int a_col = (lane >> 4) * 8;               // halves
    int b_row = (lane & 7) + (lane >> 4) * 8;
    int b_col = ((lane >> 3) & 1) * 8;
    uint32_t smbase = smem_u32(smh);
    uint32_t qa_base = smbase + ((wid*16 + a_row)*FQ_LDH + a_col) * 2;
    uint32_t kb_off  = (b_row*FQ_LDH + b_col) * 2;
    uint32_t va_off  = (a_row*FQ_LDH + a_col) * 2;

    auto issueKV = [&](int kt) {
        __half* Kd = smh + ((kt & 1) ? FA_K1_H : FA_K0_H);
        __half* Vd = smh + ((kt & 1) ? FA_V1_H : FA_V0_H);
        const __half* Kg = qb + EE   + (long)(kt*128)*E3;
        const __half* Vg = qb + 2*EE + (long)(kt*128)*E3;
        #pragma unroll
        for (int p = 0; p < 8; p++) {
            int idx = p*256 + tid;
            int r = idx >> 4, c8 = (idx & 15) << 3;
            CP_ASYNC16(smem_u32(Kd + r*FQ_LDH + c8), Kg + (long)r*E3 + c8);
        }
        #pragma unroll
        for (int p = 0; p < 8; p++) {
            int idx = p*256 + tid;
            int r = idx >> 4, c8 = (idx & 15) << 3;
            CP_ASYNC16(smem_u32(Vd + r*FQ_LDH + c8), Vg + (long)r*E3 + c8);
        }
        CP_COMMIT();
    };

    {   // Q tile 128 x 128 halves
        const __half* Qg = qb + (long)(qt*128)*E3;
        #pragma unroll
        for (int p = 0; p < 8; p++) {
            int idx = p*256 + tid;
            int r = idx >> 4, c8 = (idx & 15) << 3;
            CP_ASYNC16(smem_u32(Qs + r*FQ_LDH + c8), Qg + (long)r*E3 + c8);
        }
    }
    issueKV(0);

    float o[16][4];
    #pragma unroll
    for (int nt = 0; nt < 16; nt++)
        #pragma unroll
        for (int r = 0; r < 4; r++) o[nt][r] = 0.f;
    float m0 = -1e30f, m1 = -1e30f, l0 = 0.f, l1 = 0.f;

    int rowg0 = qt*128 + wid*16 + gq;
    int rowg1 = rowg0 + 8;
    int nkt = qt + 1;

    for (int kt = 0; kt < nkt; kt++) {
        CP_WAIT(0);
        __syncthreads();                 // K(kt),V(kt) ready; buffers (kt+1)&1 free
        if (kt + 1 < nkt) issueKV(kt + 1);

        uint32_t kb_base = smbase
            + (uint32_t)(((kt & 1) ? FA_K1_H : FA_K0_H) * 2) + kb_off;
        uint32_t vb_base = smbase
            + (uint32_t)(((kt & 1) ? FA_V1_H : FA_V0_H) * 2) + va_off;

        // ---- S = Q K^T (16 rows x 128 cols / warp) ----
        float s[16][4];
        #pragma unroll
        for (int nt = 0; nt < 16; nt++)
            #pragma unroll
            for (int r = 0; r < 4; r++) s[nt][r] = 0.f;

        #pragma unroll
        for (int ks = 0; ks < 8; ks++) {       // D=128 / k16
            uint32_t kcb = ks * 32;
            uint32_t a[4];
            ldsm4(a, qa_base + kcb);
            #pragma unroll
            for (int np = 0; np < 8; np++) {   // 128 cols / n16
                uint32_t bm[4];
                ldsm4(bm, kb_base + np*(16*FQ_LDH*2) + kcb);
                mma16(s[2*np],   a, &bm[0]);
                mma16(s[2*np+1], a, &bm[2]);
            }
        }

        // ---- causal mask: only the diagonal block is partial ----
        if (kt == qt) {
            #pragma unroll
            for (int nt = 0; nt < 16; nt++) {
                int col = kt*128 + nt*8 + 2*tg;
                if (col   > rowg0) s[nt][0] = -1e30f;
                if (col+1 > rowg0) s[nt][1] = -1e30f;
                if (col   > rowg1) s[nt][2] = -1e30f;
                if (col+1 > rowg1) s[nt][3] = -1e30f;
            }
        }

        // ---- online softmax (fp32) ----
        float mt0 = -1e30f, mt1 = -1e30f;
        #pragma unroll
        for (int nt = 0; nt < 16; nt++) {
            mt0 = fmaxf(mt0, fmaxf(s[nt][0], s[nt][1]));
            mt1 = fmaxf(mt1, fmaxf(s[nt][2], s[nt][3]));
        }
        mt0 = fmaxf(mt0, __shfl_xor_sync(0xffffffffu, mt0, 1));
        mt0 = fmaxf(mt0, __shfl_xor_sync(0xffffffffu, mt0, 2));
        mt1 = fmaxf(mt1, __shfl_xor_sync(0xffffffffu, mt1, 1));
        mt1 = fmaxf(mt1, __shfl_xor_sync(0xffffffffu, mt1, 2));

        float mn0 = fmaxf(m0, mt0), mn1 = fmaxf(m1, mt1);
        float c0 = __expf(m0 - mn0), c1 = __expf(m1 - mn1);

        float sum0 = 0.f, sum1 = 0.f;
        uint32_t ph[32];
        #pragma unroll
        for (int nt = 0; nt < 16; nt++) {
            s[nt][0] = __expf(s[nt][0] - mn0);
            s[nt][1] = __expf(s[nt][1] - mn0);
            s[nt][2] = __expf(s[nt][2] - mn1);
            s[nt][3] = __expf(s[nt][3] - mn1);
            sum0 += s[nt][0] + s[nt][1];
            sum1 += s[nt][2] + s[nt][3];
            ph[2*nt]   = h2pack(s[nt][0], s[nt][1]);
            ph[2*nt+1] = h2pack(s[nt][2], s[nt][3]);
        }
        sum0 += __shfl_xor_sync(0xffffffffu, sum0, 1);
        sum0 += __shfl_xor_sync(0xffffffffu, sum0, 2);
        sum1 += __shfl_xor_sync(0xffffffffu, sum1, 1);
        sum1 += __shfl_xor_sync(0xffffffffu, sum1, 2);

        l0 = l0*c0 + sum0;  l1 = l1*c1 + sum1;
        m0 = mn0;           m1 = mn1;

        #pragma unroll
        for (int nt = 0; nt < 16; nt++) {
            o[nt][0] *= c0; o[nt][1] *= c0;
            o[nt][2] *= c1; o[nt][3] *= c1;
        }

        // ---- O += P @ V : P fed straight from registers ----
        #pragma unroll
        for (int ks = 0; ks < 8; ks++) {       // 128 k / k16
            uint32_t v_base = vb_base + (uint32_t)(ks*16*FQ_LDH*2);
            #pragma unroll
            for (int np = 0; np < 8; np++) {   // 128 n / n16
                uint32_t vb[4];
                ldsm4t(vb, v_base + np*32);
                mma16(o[2*np],   &ph[4*ks], &vb[0]);
                mma16(o[2*np+1], &ph[4*ks], &vb[2]);
            }
        }
        // no bottom barrier: V is double-buffered; top-of-loop barrier protects
    }

    // ---- normalize + store half ctx ----
    float i0 = 1.f/l0, i1 = 1.f/l1;
    __half* cb0 = ctx + (long)b*SS*EE + (long)rowg0*EE + h*DD;
    __half* cb1 = cb0 + 8*EE;
    #pragma unroll
    for (int nt = 0; nt < 16; nt++) {
        int col = nt*8 + 2*tg;
        __half2 v0 = __floats2half2_rn(o[nt][0]*i0, o[nt][1]*i0);
        __half2 v1 = __floats2half2_rn(o[nt][2]*i1, o[nt][3]*i1);
        *(__half2*)(cb0 + col) = v0;
        *(__half2*)(cb1 + col) = v1;
    }
}

// ---------------------------------------------------------------------------
// RoPE in place on half q,k (q also pre-scaled by 1/sqrt(D)). v untouched.
// ---------------------------------------------------------------------------
__global__ __launch_bounds__(256)
void rope_k(__half* __restrict__ qkvh)
{
    long t = (long)blockIdx.x * blockDim.x + threadIdx.x;
    int j = (int)(t & 63);
    int h = (int)((t >> 6) & (HH_-1));
    long bs = t >> 10;
    int s = (int)(bs & (SS-1));

    const float scale = 0.08838834764831845f;  // 1/sqrt(128)
    float inv = powf(10000.f, -((float)(2*j)) * (1.f/128.f));
    float fr  = (float)s * inv;
    float c, sn;
    sincosf(fr, &sn, &c);

    __half* qh = qkvh + bs*(long)E3 + (long)h*DD;
    float q1 = __half2float(qh[j]), q2 = __half2float(qh[j+64]);
    qh[j]    = __float2half_rn((q1*c - q2*sn) * scale);
    qh[j+64] = __float2half_rn((q1*sn + q2*c) * scale);

    __half* kh = qh + EE;
    float k1 = __half2float(kh[j]), k2 = __half2float(kh[j+64]);
    kh[j]    = __float2half_rn(k1*c - k2*sn);
    kh[j+64] = __float2half_rn(k1*sn + k2*c);
}

// ---------------------------------------------------------------------------
extern "C" void kernel_launch(void* const* d_in, const int* in_sizes, int n_in,
                              void* d_out, int out_size)
{
    const float* x      = (const float*)d_in[0];
    const float* wqkv_w = (const float*)d_in[1];
    const float* wqkv_b = (const float*)d_in[2];
    const float* out_w  = (const float*)d_in[3];
    const float* out_b  = (const float*)d_in[4];
    float*       out    = (float*)d_out;

    __half *qkvh, *ctxh, *xh, *w1h, *w2h;
    cudaGetSymbolAddress((void**)&qkvh, g_qkvh);
    cudaGetSymbolAddress((void**)&ctxh, g_ctxh);
    cudaGetSymbolAddress((void**)&xh,   g_xh);
    cudaGetSymbolAddress((void**)&w1h,  g_w1h);
    cudaGetSymbolAddress((void**)&w2h,  g_w2h);

    cudaFuncSetAttribute(tqkv96,
        cudaFuncAttributeMaxDynamicSharedMemorySize, SMEM_QKV);
    cudaFuncSetAttribute(tout256,
        cudaFuncAttributeMaxDynamicSharedMemorySize, SMEM_OUT);
    cudaFuncSetAttribute(fa_k,
        cudaFuncAttributeMaxDynamicSharedMemorySize, FA_SMEM);

    const int Mx = BB*SS;             // 4096

    // 0) fp16 copies of GEMM inputs
    h16copy_k<<<(unsigned)(((long)Mx*EE)/2048), 256>>>(x, xh);
    h16copy_k<<<(unsigned)(((long)E3*EE)/2048), 256>>>(wqkv_w, w1h);
    h16copy_k<<<(unsigned)(((long)EE*EE)/2048), 256>>>(out_w, w2h);

    // 1) QKV projection: 128x96 tiles, 2 CTAs/SM -> 2048 CTAs = 6.92 waves
    {
        dim3 g(E3/Q_BN, Mx/128, 1);
        tqkv96<<<g,256,SMEM_QKV>>>(xh, w1h, qkvh, wqkv_b, EE, EE, EE, E3);
    }
    // 2) RoPE in place on half q,k
    {
        long total = (long)BB*SS*HH_*64;
        rope_k<<<(unsigned)(total/256), 256>>>(qkvh);
    }
    // 3) fused flash attention -> half ctx (P in regs, K+V double-buffered)
    {
        dim3 g(SS/128, BB*HH_);
        fa_k<<<g,256,FA_SMEM>>>(qkvh, ctxh);
    }
    // 4) output projection (fp16 in, fp32 out + bias)
    {
        dim3 g(EE/O_BN, Mx/128, 1);
        tout256<<<g,256,SMEM_OUT>>>(ctxh, w2h, out, out_b, EE, EE, EE, EE);
    }
}

// round 16
// speedup vs baseline: 1.0576x; 1.0576x over previous
#include <cuda_runtime.h>
#include <cuda_fp16.h>
#include <math.h>
#include <cstdint>

// Problem constants
#define BB 2
#define SS 2048
#define EE 2048
#define HH_ 16
#define DD 128
#define E3 (3*EE)

// Scratch (allocation-free rule: __device__ globals)
__device__ __half g_qkvh[(long)BB*SS*E3];   // half qkv (gemm out, rope in-place, FA in)
__device__ __half g_ctxh[(long)BB*SS*EE];   // half ctx (FA out, out-proj in)
__device__ __half g_xh [(long)BB*SS*EE];
__device__ __half g_w1h[(long)E3*EE];
__device__ __half g_w2h[(long)EE*EE];

__device__ __forceinline__ void mma16(float* d, const uint32_t* a, const uint32_t* b) {
    asm volatile("mma.sync.aligned.m16n8k16.row.col.f32.f16.f16.f32 "
        "{%0,%1,%2,%3}, {%4,%5,%6,%7}, {%8,%9}, {%0,%1,%2,%3};"
        : "+f"(d[0]), "+f"(d[1]), "+f"(d[2]), "+f"(d[3])
        : "r"(a[0]), "r"(a[1]), "r"(a[2]), "r"(a[3]), "r"(b[0]), "r"(b[1]));
}
__device__ __forceinline__ void ldsm4(uint32_t* r, uint32_t addr) {
    asm volatile("ldmatrix.sync.aligned.m8n8.x4.shared.b16 {%0,%1,%2,%3}, [%4];"
        : "=r"(r[0]), "=r"(r[1]), "=r"(r[2]), "=r"(r[3]) : "r"(addr));
}
__device__ __forceinline__ void ldsm4t(uint32_t* r, uint32_t addr) {
    asm volatile("ldmatrix.sync.aligned.m8n8.x4.trans.shared.b16 {%0,%1,%2,%3}, [%4];"
        : "=r"(r[0]), "=r"(r[1]), "=r"(r[2]), "=r"(r[3]) : "r"(addr));
}
__device__ __forceinline__ uint32_t smem_u32(const void* p) {
    uint32_t a;
    asm("{ .reg .u64 t; cvta.to.shared.u64 t, %1; cvt.u32.u64 %0, t; }"
        : "=r"(a) : "l"(p));
    return a;
}
__device__ __forceinline__ uint32_t h2pack(float lo, float hi) {
    __half2 h = __floats2half2_rn(lo, hi);
    return *(uint32_t*)&h;
}
#define CP_ASYNC16(dst, src) \
    asm volatile("cp.async.ca.shared.global [%0], [%1], 16;" :: "r"(dst), "l"(src))
#define CP_COMMIT() asm volatile("cp.async.commit_group;" ::: "memory")
#define CP_WAIT(n)  asm volatile("cp.async.wait_group %0;" :: "n"(n) : "memory")

// ---------------------------------------------------------------------------
// Fused fp32 -> fp16 round-copy of x, wqkv_w, out_w (one launch).
// Block counts: x 4096, w1 6144, w2 2048 (2048 floats per block).
// ---------------------------------------------------------------------------
__global__ __launch_bounds__(256)
void h16copy3_k(const float* __restrict__ x,  __half* __restrict__ xh,
                const float* __restrict__ w1, __half* __restrict__ w1h,
                const float* __restrict__ w2, __half* __restrict__ w2h)
{
    const float* in; __half* out; long base;
    int bid = blockIdx.x;
    if (bid < 4096)        { in = x;  out = xh;  base = (long)bid * 2048; }
    else if (bid < 10240)  { in = w1; out = w1h; base = (long)(bid - 4096) * 2048; }
    else                   { in = w2; out = w2h; base = (long)(bid - 10240) * 2048; }

    long i = base + (long)threadIdx.x * 8;
    float4 v0 = *(const float4*)(in + i);
    float4 v1 = *(const float4*)(in + i + 4);
    __half2 h0 = __floats2half2_rn(v0.x, v0.y);
    __half2 h1 = __floats2half2_rn(v0.z, v0.w);
    __half2 h2 = __floats2half2_rn(v1.x, v1.y);
    __half2 h3 = __floats2half2_rn(v1.z, v1.w);
    uint4 o;
    o.x = *(uint32_t*)&h0; o.y = *(uint32_t*)&h1;
    o.z = *(uint32_t*)&h2; o.w = *(uint32_t*)&h3;
    *(uint4*)(out + i) = o;
}

// ===========================================================================
// fp16 pipelined GEMM (TRANSB): C[m,n]= sum_k A[m,k]*B[n,k] (+bias)
// CTA tile 128xBN (BN=192 QKV -> 1024 CTAs = 6.92 waves; BN=256 out-proj),
// 8 warps (2x4), BK=64 halves, 3-stage cp.async, ldmatrix, m16n8k16.
// QKVMODE: outputs written as half to gCh (rope rotates q,k in place).
// ===========================================================================
#define BM2 128
#define BKH 64
#define LDH 72                      // halves; 36 words -> 4-bank shift/row

template<int BN, bool BIAS, bool QKVMODE>
__global__ __launch_bounds__(256)
void tgemm2h(const __half* __restrict__ gA, const __half* __restrict__ gB,
             float* __restrict__ gC, __half* __restrict__ gCh,
             const float* __restrict__ bias,
             int K, int lda, int ldb, int ldc)
{
    constexpr int NP   = BN / 64;
    constexpr int NT   = BN / 32;
    constexpr int A_ST = 128 * LDH;
    constexpr int B_ST = BN * LDH;
    constexpr int STH  = A_ST + B_ST;

    extern __shared__ __half smh[];
    int m0 = blockIdx.y * BM2;
    int n0 = blockIdx.x * BN;
    int niter = K / BKH;

    int tid  = threadIdx.x;
    int wid  = tid >> 5;
    int lane = tid & 31;
    int wm = wid & 1;
    int wn = wid >> 1;
    int gq = lane >> 2;
    int tg = lane & 3;

    int a_row = (lane & 7) + ((lane >> 3) & 1) * 8;
    int a_col = (lane >> 4) * 8;
    int b_row = (lane & 7) + (lane >> 4) * 8;
    int b_col = ((lane >> 3) & 1) * 8;
    uint32_t smbase = smem_u32(smh);
    uint32_t aoff = ((wm*64 + a_row) * LDH + a_col) * 2;
    uint32_t boff = (uint32_t)(A_ST*2) + ((wn*(BN/4) + b_row) * LDH + b_col) * 2;

    float acc[4][NT][4];
    #pragma unroll
    for (int mt = 0; mt < 4; mt++)
        #pragma unroll
        for (int nt = 0; nt < NT; nt++)
            #pragma unroll
            for (int r = 0; r < 4; r++) acc[mt][nt][r] = 0.f;

    auto issue = [&](int it) {
        int k0 = it * BKH;
        __half* As = smh + (it % 3) * STH;
        __half* Bs = As + A_ST;
        const __half* Ab = gA + (long)m0 * lda + k0;
        #pragma unroll
        for (int p = 0; p < 4; p++) {
            int idx = p * 256 + tid;
            int r = idx >> 3, c8 = (idx & 7) << 3;
            CP_ASYNC16(smem_u32(As + r * LDH + c8), Ab + (long)r * lda + c8);
        }
        const __half* Bb = gB + (long)n0 * ldb + k0;
        #pragma unroll
        for (int p = 0; p < BN/32; p++) {
            int idx = p * 256 + tid;
            int r = idx >> 3, c8 = (idx & 7) << 3;
            CP_ASYNC16(smem_u32(Bs + r * LDH + c8), Bb + (long)r * ldb + c8);
        }
        CP_COMMIT();
    };

    auto compute = [&](int s) {
        uint32_t a_base = smbase + s*(STH*2) + aoff;
        uint32_t b_base = smbase + s*(STH*2) + boff;
        #pragma unroll
        for (int ks = 0; ks < 4; ks++) {
            uint32_t kcb = ks * 32;
            uint32_t a[4][4], b[NP][4];
            #pragma unroll
            for (int mt = 0; mt < 4; mt++)
                ldsm4(a[mt], a_base + mt*(16*LDH*2) + kcb);
            #pragma unroll
            for (int np = 0; np < NP; np++)
                ldsm4(b[np], b_base + np*(16*LDH*2) + kcb);
            #pragma unroll
            for (int mt = 0; mt < 4; mt++)
                #pragma unroll
                for (int np = 0; np < NP; np++) {
                    mma16(acc[mt][2*np],   a[mt], &b[np][0]);
                    mma16(acc[mt][2*np+1], a[mt], &b[np][2]);
                }
        }
    };

    issue(0);
    if (niter > 1) issue(1);
    for (int it = 0; it < niter; ++it) {
        if (it + 1 < niter) CP_WAIT(1); else CP_WAIT(0);
        __syncthreads();
        if (it + 2 < niter) issue(it + 2);
        compute(it % 3);
    }

    #pragma unroll
    for (int mt = 0; mt < 4; mt++) {
        int row = m0 + wm*64 + mt*16 + gq;
        #pragma unroll
        for (int nt = 0; nt < NT; nt++) {
            int col = n0 + wn*(BN/4) + nt*8 + 2*tg;
            float b0 = 0.f, b1 = 0.f;
            if (BIAS) { b0 = bias[col]; b1 = bias[col + 1]; }
            float2 v0, v1;
            v0.x = acc[mt][nt][0] + b0; v0.y = acc[mt][nt][1] + b1;
            v1.x = acc[mt][nt][2] + b0; v1.y = acc[mt][nt][3] + b1;
            if (QKVMODE) {
                *(__half2*)(gCh + (long)row * ldc + col)
                    = __floats2half2_rn(v0.x, v0.y);
                *(__half2*)(gCh + (long)(row + 8) * ldc + col)
                    = __floats2half2_rn(v1.x, v1.y);
            } else {
                *(float2*)(gC + (long)row * ldc + col)       = v0;
                *(float2*)(gC + (long)(row + 8) * ldc + col) = v1;
            }
        }
    }
}

// ===========================================================================
// fp16 flash attention, 128-col K-tiles; P in registers; K AND V double-
// buffered -> single barrier + single commit group per iteration.
// Smem halves: Q | K0 | K1 | V0 | V1, each 128x136 = 87040 halves = 174080 B
// ===========================================================================
#define FQ_LDH 136
#define FA_K0_H (128*FQ_LDH)
#define FA_K1_H (FA_K0_H + 128*FQ_LDH)
#define FA_V0_H (FA_K1_H + 128*FQ_LDH)
#define FA_V1_H (FA_V0_H + 128*FQ_LDH)
#define FA_SMEM ((FA_V1_H + 128*FQ_LDH)*2)

__global__ __launch_bounds__(256)
void fa_k(const __half* __restrict__ qkv, __half* __restrict__ ctx)
{
    extern __shared__ __half smh[];
    __half* Qs = smh;

    int qt = gridDim.x - 1 - blockIdx.x;       // heavy tiles first
    int bh = blockIdx.y;
    int b = bh >> 4, h = bh & 15;
    const __half* qb = qkv + (long)b*SS*E3 + (long)h*DD;

    int tid = threadIdx.x, wid = tid >> 5, lane = tid & 31;
    int gq = lane >> 2, tg = lane & 3;

    int a_row = (lane & 7) + ((lane >> 3) & 1) * 8;
    int a_col = (lane >> 4) * 8;               // halves
    int b_row = (lane & 7) + (lane >> 4) * 8;
    int b_col = ((lane >> 3) & 1) * 8;
    uint32_t smbase = smem_u32(smh);
    uint32_t qa_base = smbase + ((wid*16 + a_row)*FQ_LDH + a_col) * 2;
    uint32_t kb_off  = (b_row*FQ_LDH + b_col) * 2;
    uint32_t va_off  = (a_row*FQ_LDH + a_col) * 2;

    auto issueKV = [&](int kt) {
        __half* Kd = smh + ((kt & 1) ? FA_K1_H : FA_K0_H);
        __half* Vd = smh + ((kt & 1) ? FA_V1_H : FA_V0_H);
        const __half* Kg = qb + EE   + (long)(kt*128)*E3;
        const __half* Vg = qb + 2*EE + (long)(kt*128)*E3;
        #pragma unroll
        for (int p = 0; p < 8; p++) {
            int idx = p*256 + tid;
            int r = idx >> 4, c8 = (idx & 15) << 3;
            CP_ASYNC16(smem_u32(Kd + r*FQ_LDH + c8), Kg + (long)r*E3 + c8);
        }
        #pragma unroll
        for (int p = 0; p < 8; p++) {
            int idx = p*256 + tid;
            int r = idx >> 4, c8 = (idx & 15) << 3;
            CP_ASYNC16(smem_u32(Vd + r*FQ_LDH + c8), Vg + (long)r*E3 + c8);
        }
        CP_COMMIT();
    };

    {   // Q tile 128 x 128 halves
        const __half* Qg = qb + (long)(qt*128)*E3;
        #pragma unroll
        for (int p = 0; p < 8; p++) {
            int idx = p*256 + tid;
            int r = idx >> 4, c8 = (idx & 15) << 3;
            CP_ASYNC16(smem_u32(Qs + r*FQ_LDH + c8), Qg + (long)r*E3 + c8);
        }
    }
    issueKV(0);

    float o[16][4];
    #pragma unroll
    for (int nt = 0; nt < 16; nt++)
        #pragma unroll
        for (int r = 0; r < 4; r++) o[nt][r] = 0.f;
    float m0 = -1e30f, m1 = -1e30f, l0 = 0.f, l1 = 0.f;

    int rowg0 = qt*128 + wid*16 + gq;
    int rowg1 = rowg0 + 8;
    int nkt = qt + 1;

    for (int kt = 0; kt < nkt; kt++) {
        CP_WAIT(0);
        __syncthreads();                 // K(kt),V(kt) ready; buffers (kt+1)&1 free
        if (kt + 1 < nkt) issueKV(kt + 1);

        uint32_t kb_base = smbase
            + (uint32_t)(((kt & 1) ? FA_K1_H : FA_K0_H) * 2) + kb_off;
        uint32_t vb_base = smbase
            + (uint32_t)(((kt & 1) ? FA_V1_H : FA_V0_H) * 2) + va_off;

        // ---- S = Q K^T (16 rows x 128 cols / warp) ----
        float s[16][4];
        #pragma unroll
        for (int nt = 0; nt < 16; nt++)
            #pragma unroll
            for (int r = 0; r < 4; r++) s[nt][r] = 0.f;

        #pragma unroll
        for (int ks = 0; ks < 8; ks++) {       // D=128 / k16
            uint32_t kcb = ks * 32;
            uint32_t a[4];
            ldsm4(a, qa_base + kcb);
            #pragma unroll
            for (int np = 0; np < 8; np++) {   // 128 cols / n16
                uint32_t bm[4];
                ldsm4(bm, kb_base + np*(16*FQ_LDH*2) + kcb);
                mma16(s[2*np],   a, &bm[0]);
                mma16(s[2*np+1], a, &bm[2]);
            }
        }

        // ---- causal mask: only the diagonal block is partial ----
        if (kt == qt) {
            #pragma unroll
            for (int nt = 0; nt < 16; nt++) {
                int col = kt*128 + nt*8 + 2*tg;
                if (col   > rowg0) s[nt][0] = -1e30f;
                if (col+1 > rowg0) s[nt][1] = -1e30f;
                if (col   > rowg1) s[nt][2] = -1e30f;
                if (col+1 > rowg1) s[nt][3] = -1e30f;
            }
        }

        // ---- online softmax (fp32) ----
        float mt0 = -1e30f, mt1 = -1e30f;
        #pragma unroll
        for (int nt = 0; nt < 16; nt++) {
            mt0 = fmaxf(mt0, fmaxf(s[nt][0], s[nt][1]));
            mt1 = fmaxf(mt1, fmaxf(s[nt][2], s[nt][3]));
        }
        mt0 = fmaxf(mt0, __shfl_xor_sync(0xffffffffu, mt0, 1));
        mt0 = fmaxf(mt0, __shfl_xor_sync(0xffffffffu, mt0, 2));
        mt1 = fmaxf(mt1, __shfl_xor_sync(0xffffffffu, mt1, 1));
        mt1 = fmaxf(mt1, __shfl_xor_sync(0xffffffffu, mt1, 2));

        float mn0 = fmaxf(m0, mt0), mn1 = fmaxf(m1, mt1);
        float c0 = __expf(m0 - mn0), c1 = __expf(m1 - mn1);

        float sum0 = 0.f, sum1 = 0.f;
        uint32_t ph[32];
        #pragma unroll
        for (int nt = 0; nt < 16; nt++) {
            s[nt][0] = __expf(s[nt][0] - mn0);
            s[nt][1] = __expf(s[nt][1] - mn0);
            s[nt][2] = __expf(s[nt][2] - mn1);
            s[nt][3] = __expf(s[nt][3] - mn1);
            sum0 += s[nt][0] + s[nt][1];
            sum1 += s[nt][2] + s[nt][3];
            ph[2*nt]   = h2pack(s[nt][0], s[nt][1]);
            ph[2*nt+1] = h2pack(s[nt][2], s[nt][3]);
        }
        sum0 += __shfl_xor_sync(0xffffffffu, sum0, 1);
        sum0 += __shfl_xor_sync(0xffffffffu, sum0, 2);
        sum1 += __shfl_xor_sync(0xffffffffu, sum1, 1);
        sum1 += __shfl_xor_sync(0xffffffffu, sum1, 2);

        l0 = l0*c0 + sum0;  l1 = l1*c1 + sum1;
        m0 = mn0;           m1 = mn1;

        #pragma unroll
        for (int nt = 0; nt < 16; nt++) {
            o[nt][0] *= c0; o[nt][1] *= c0;
            o[nt][2] *= c1; o[nt][3] *= c1;
        }

        // ---- O += P @ V : P fed straight from registers ----
        #pragma unroll
        for (int ks = 0; ks < 8; ks++) {       // 128 k / k16
            uint32_t v_base = vb_base + (uint32_t)(ks*16*FQ_LDH*2);
            #pragma unroll
            for (int np = 0; np < 8; np++) {   // 128 n / n16
                uint32_t vb[4];
                ldsm4t(vb, v_base + np*32);
                mma16(o[2*np],   &ph[4*ks], &vb[0]);
                mma16(o[2*np+1], &ph[4*ks], &vb[2]);
            }
        }
        // no bottom barrier: V double-buffered; top-of-loop barrier protects
    }

    // ---- normalize + store half ctx ----
    float i0 = 1.f/l0, i1 = 1.f/l1;
    __half* cb0 = ctx + (long)b*SS*EE + (long)rowg0*EE + h*DD;
    __half* cb1 = cb0 + 8*EE;
    #pragma unroll
    for (int nt = 0; nt < 16; nt++) {
        int col = nt*8 + 2*tg;
        __half2 v0 = __floats2half2_rn(o[nt][0]*i0, o[nt][1]*i0);
        __half2 v1 = __floats2half2_rn(o[nt][2]*i1, o[nt][3]*i1);
        *(__half2*)(cb0 + col) = v0;
        *(__half2*)(cb1 + col) = v1;
    }
}

// ---------------------------------------------------------------------------
// RoPE in place on half q,k (q also pre-scaled by 1/sqrt(D)). v untouched.
// ---------------------------------------------------------------------------
__global__ __launch_bounds__(256)
void rope_k(__half* __restrict__ qkvh)
{
    long t = (long)blockIdx.x * blockDim.x + threadIdx.x;
    int j = (int)(t & 63);
    int h = (int)((t >> 6) & (HH_-1));
    long bs = t >> 10;
    int s = (int)(bs & (SS-1));

    const float scale = 0.08838834764831845f;  // 1/sqrt(128)
    float inv = powf(10000.f, -((float)(2*j)) * (1.f/128.f));
    float fr  = (float)s * inv;
    float c, sn;
    sincosf(fr, &sn, &c);

    __half* qh = qkvh + bs*(long)E3 + (long)h*DD;
    float q1 = __half2float(qh[j]), q2 = __half2float(qh[j+64]);
    qh[j]    = __float2half_rn((q1*c - q2*sn) * scale);
    qh[j+64] = __float2half_rn((q1*sn + q2*c) * scale);

    __half* kh = qh + EE;
    float k1 = __half2float(kh[j]), k2 = __half2float(kh[j+64]);
    kh[j]    = __float2half_rn(k1*c - k2*sn);
    kh[j+64] = __float2half_rn(k1*sn + k2*c);
}

// ---------------------------------------------------------------------------
extern "C" void kernel_launch(void* const* d_in, const int* in_sizes, int n_in,
                              void* d_out, int out_size)
{
    const float* x      = (const float*)d_in[0];
    const float* wqkv_w = (const float*)d_in[1];
    const float* wqkv_b = (const float*)d_in[2];
    const float* out_w  = (const float*)d_in[3];
    const float* out_b  = (const float*)d_in[4];
    float*       out    = (float*)d_out;

    __half *qkvh, *ctxh, *xh, *w1h, *w2h;
    cudaGetSymbolAddress((void**)&qkvh, g_qkvh);
    cudaGetSymbolAddress((void**)&ctxh, g_ctxh);
    cudaGetSymbolAddress((void**)&xh,   g_xh);
    cudaGetSymbolAddress((void**)&w1h,  g_w1h);
    cudaGetSymbolAddress((void**)&w2h,  g_w2h);

    const int SMEM_QKV = 3*(128+192)*LDH*2;   // 138240
    const int SMEM_OUT = 3*(128+256)*LDH*2;   // 165888
    cudaFuncSetAttribute(tgemm2h<192,true,true>,
        cudaFuncAttributeMaxDynamicSharedMemorySize, SMEM_QKV);
    cudaFuncSetAttribute(tgemm2h<256,true,false>,
        cudaFuncAttributeMaxDynamicSharedMemorySize, SMEM_OUT);
    cudaFuncSetAttribute(fa_k,
        cudaFuncAttributeMaxDynamicSharedMemorySize, FA_SMEM);

    const int Mx = BB*SS;             // 4096

    // 0) fused fp16 copies of x, wqkv_w, out_w (one launch)
    h16copy3_k<<<12288, 256>>>(x, xh, wqkv_w, w1h, out_w, w2h);

    // 1) QKV projection: 128x192 tiles -> 1024 CTAs; half output direct
    {
        dim3 g(E3/192, Mx/BM2, 1);
        tgemm2h<192,true,true><<<g,256,SMEM_QKV>>>(
            xh, w1h, nullptr, qkvh, wqkv_b, EE, EE, EE, E3);
    }
    // 2) RoPE in place on half q,k
    {
        long total = (long)BB*SS*HH_*64;
        rope_k<<<(unsigned)(total/256), 256>>>(qkvh);
    }
    // 3) fused flash attention -> half ctx (P in regs, K+V double-buffered)
    {
        dim3 g(SS/128, BB*HH_);
        fa_k<<<g,256,FA_SMEM>>>(qkvh, ctxh);
    }
    // 4) output projection (fp16 in, fp32 out + bias)
    {
        dim3 g(EE/256, Mx/BM2, 1);
        tgemm2h<256,true,false><<<g,256,SMEM_OUT>>>(
            ctxh, w2h, out, nullptr, out_b, EE, EE, EE, EE);
    }
}